// round 12
// baseline (speedup 1.0000x reference)
#include <cuda_runtime.h>
#include <cuda_fp16.h>
#include <cstdint>

// Problem constants
#define SEQ    4096
#define DMODEL 1024
#define D3     3072
#define NHEAD  16
#define HDIM   64
#define WIN    512
#define NCHUNK 8

// Scratch (device globals: allocation-free per harness rules)
__device__ __half g_qkvh[SEQ * D3];           // qkv hi plane (x256)
__device__ __half g_qkvl[SEQ * D3];           // qkv lo plane
__device__ __half g_xh[SEQ * DMODEL];
__device__ __half g_xl[SEQ * DMODEL];
__device__ __half g_wqh[D3 * DMODEL];         // w_qkv^T planes [N][K]
__device__ __half g_wql[D3 * DMODEL];
__device__ __half g_ath[SEQ * DMODEL];        // attn split planes (x256)
__device__ __half g_atl[SEQ * DMODEL];
__device__ __half g_woh[DMODEL * DMODEL];     // w_out^T planes [N][K]
__device__ __half g_wol[DMODEL * DMODEL];

// ---------------------------------------------------------------------------
// helpers
// ---------------------------------------------------------------------------
__device__ __forceinline__ void split_h(float x, __half& hi, __half& lo) {
    hi = __float2half_rn(x);
    lo = __float2half_rn(x - __half2float(hi));
}
__device__ __forceinline__ uint32_t split_pack(float x, float y, uint32_t& lo) {
    __half2 h2 = __float22half2_rn(make_float2(x, y));
    float2 hf = __half22float2(h2);
    __half2 l2 = __float22half2_rn(make_float2(x - hf.x, y - hf.y));
    lo = *reinterpret_cast<uint32_t*>(&l2);
    return *reinterpret_cast<uint32_t*>(&h2);
}
__device__ __forceinline__ float fexp2(float x) {
    float r;
    asm("ex2.approx.f32 %0, %1;" : "=f"(r) : "f"(x));
    return r;
}

#define MMA_F16(d, a0, a1, a2, a3, b0, b1)                                     \
    asm volatile(                                                              \
        "mma.sync.aligned.m16n8k16.row.col.f32.f16.f16.f32 "                   \
        "{%0,%1,%2,%3}, {%4,%5,%6,%7}, {%8,%9}, {%0,%1,%2,%3};"                \
        : "+f"((d)[0]), "+f"((d)[1]), "+f"((d)[2]), "+f"((d)[3])               \
        : "r"(a0), "r"(a1), "r"(a2), "r"(a3), "r"(b0), "r"(b1))

#define LDSM_X4(r0, r1, r2, r3, addr)                                          \
    asm volatile("ldmatrix.sync.aligned.m8n8.x4.shared.b16 {%0,%1,%2,%3}, [%4];" \
        : "=r"(r0), "=r"(r1), "=r"(r2), "=r"(r3) : "r"(addr))

#define LDSM_X4_T(r0, r1, r2, r3, addr)                                        \
    asm volatile("ldmatrix.sync.aligned.m8n8.x4.trans.shared.b16 {%0,%1,%2,%3}, [%4];" \
        : "=r"(r0), "=r"(r1), "=r"(r2), "=r"(r3) : "r"(addr))

#define CP_ASYNC16(dst, src)                                                   \
    asm volatile("cp.async.cg.shared.global [%0], [%1], 16;"                   \
        :: "r"(dst), "l"(src))
#define CP_COMMIT()  asm volatile("cp.async.commit_group;" ::: "memory")
#define CP_WAIT0()   asm volatile("cp.async.wait_group 0;" ::: "memory")

// ---------------------------------------------------------------------------
// Split kernels (unchanged)
// ---------------------------------------------------------------------------
__global__ __launch_bounds__(256) void split2h(const float* __restrict__ in,
                                               __half* __restrict__ hp,
                                               __half* __restrict__ lp, int n) {
    const int idx = (blockIdx.x * 256 + threadIdx.x) * 4;
    if (idx >= n) return;
    const float4 v = *(const float4*)(in + idx);
    uint32_t l0, l1;
    const uint32_t h0 = split_pack(v.x * 256.f, v.y * 256.f, l0);
    const uint32_t h1 = split_pack(v.z * 256.f, v.w * 256.f, l1);
    *(uint2*)(hp + idx) = make_uint2(h0, h1);
    *(uint2*)(lp + idx) = make_uint2(l0, l1);
}

__global__ void split2h_t(const float* __restrict__ w,
                          __half* __restrict__ th, __half* __restrict__ tl,
                          int Kd, int Nd) {
    __shared__ float tile[32][33];
    const int k0 = blockIdx.y * 32, n0 = blockIdx.x * 32;
    const int tx = threadIdx.x, ty = threadIdx.y;
    for (int r = ty; r < 32; r += 8)
        tile[r][tx] = w[(size_t)(k0 + r) * Nd + n0 + tx];
    __syncthreads();
    for (int r = ty; r < 32; r += 8) {
        __half h, l;
        split_h(tile[tx][r] * 256.f, h, l);
        const size_t o = (size_t)(n0 + r) * Kd + k0 + tx;
        th[o] = h; tl[o] = l;
    }
}

// ---------------------------------------------------------------------------
// 3xFP16 GEMM (m16n8k16), cp.async double-buffered (unchanged from R10).
// ---------------------------------------------------------------------------
template <bool SPLIT_OUT>
__global__ __launch_bounds__(256, 2) void gemm_f16x3(
    const __half* __restrict__ Ahg, const __half* __restrict__ Alg,
    const __half* __restrict__ Bhg, const __half* __restrict__ Blg,
    float* __restrict__ Cf, __half* __restrict__ Ch, __half* __restrict__ Cl,
    int M, int N, int K, float outscale) {
    extern __shared__ char smc[];

    const int tid  = threadIdx.x;
    const int lane = tid & 31;
    const int warp = tid >> 5;
    const int warp_m = warp >> 2;
    const int warp_n = warp & 3;

    const int m0 = blockIdx.y * 128;
    const int n0 = blockIdx.x * 128;

    const int lm_row  = (lane & 7) + ((lane >> 3) & 1) * 8;
    const int lm_csel = lane >> 4;
    const int bq = lane >> 2;
    const int bi = lane & 3;

    float acc[4][4][4] = {};

    const uint32_t sb = (uint32_t)__cvta_generic_to_shared(smc);
    const uint32_t* SM32 = (const uint32_t*)smc;

    const __half* base0 = Ahg + (size_t)m0 * K;
    const __half* base1 = Alg + (size_t)m0 * K;
    const __half* base2 = Bhg + (size_t)n0 * K;
    const __half* base3 = Blg + (size_t)n0 * K;

    const int NIT = K >> 5;

    auto issue = [&](int it) {
        const int k0 = it << 5;
        const int st4 = (it & 1) << 2;
        #pragma unroll
        for (int i = 0; i < 8; i++) {
            const int lin = tid + i * 256;
            const int pl  = lin >> 9;
            const int rem = lin & 511;
            const int row = rem >> 2;
            const int ch  = rem & 3;
            const __half* src =
                (pl == 0 ? base0 : pl == 1 ? base1 : pl == 2 ? base2 : base3)
                + (size_t)row * K + k0 + ch * 8;
            const uint32_t dst = sb + pl * 16384 + row * 128 +
                                 (((st4 + ch) ^ (row & 7)) << 4);
            CP_ASYNC16(dst, src);
        }
        CP_COMMIT();
    };

    issue(0);
    for (int it = 0; it < NIT; it++) {
        CP_WAIT0();
        __syncthreads();
        if (it + 1 < NIT) issue(it + 1);

        const int st4 = (it & 1) << 2;
        #pragma unroll
        for (int s = 0; s < 2; s++) {
            const int c0 = st4 + 2 * s;
            uint32_t aH[4][4], aL[4][4];
            #pragma unroll
            for (int mf = 0; mf < 4; mf++) {
                const int m = warp_m * 64 + mf * 16 + lm_row;
                const uint32_t off =
                    (uint32_t)(m * 128 + (((c0 + lm_csel) ^ (m & 7)) << 4));
                LDSM_X4(aH[mf][0], aH[mf][1], aH[mf][2], aH[mf][3], sb + off);
                LDSM_X4(aL[mf][0], aL[mf][1], aL[mf][2], aL[mf][3], sb + 16384 + off);
            }
            #pragma unroll
            for (int nf = 0; nf < 4; nf++) {
                const int n = warp_n * 32 + nf * 8 + bq;
                const int i0 = n * 32 + ((c0 ^ (n & 7)) << 2) + bi;
                const int i1 = n * 32 + (((c0 + 1) ^ (n & 7)) << 2) + bi;
                const uint32_t bh0 = SM32[8192 + i0], bh1 = SM32[8192 + i1];
                const uint32_t bl0 = SM32[12288 + i0], bl1 = SM32[12288 + i1];
                #pragma unroll
                for (int mf = 0; mf < 4; mf++) {
                    MMA_F16(acc[mf][nf], aH[mf][0], aH[mf][1], aH[mf][2], aH[mf][3], bh0, bh1);
                    MMA_F16(acc[mf][nf], aH[mf][0], aH[mf][1], aH[mf][2], aH[mf][3], bl0, bl1);
                    MMA_F16(acc[mf][nf], aL[mf][0], aL[mf][1], aL[mf][2], aL[mf][3], bh0, bh1);
                }
            }
        }
        __syncthreads();
    }

    const int row_in = lane >> 2;
    const int col_in = 2 * (lane & 3);
    #pragma unroll
    for (int mf = 0; mf < 4; mf++) {
        const int gr = m0 + warp_m * 64 + mf * 16 + row_in;
        #pragma unroll
        for (int nf = 0; nf < 4; nf++) {
            const int gc = n0 + warp_n * 32 + nf * 8 + col_in;
            if (SPLIT_OUT) {
                uint32_t lo;
                uint32_t hi = split_pack(acc[mf][nf][0] * outscale,
                                         acc[mf][nf][1] * outscale, lo);
                *(uint32_t*)(Ch + (size_t)gr * N + gc) = hi;
                *(uint32_t*)(Cl + (size_t)gr * N + gc) = lo;
                hi = split_pack(acc[mf][nf][2] * outscale,
                                acc[mf][nf][3] * outscale, lo);
                *(uint32_t*)(Ch + (size_t)(gr + 8) * N + gc) = hi;
                *(uint32_t*)(Cl + (size_t)(gr + 8) * N + gc) = lo;
            } else {
                *(float2*)(Cf + (size_t)gr * N + gc) =
                    make_float2(acc[mf][nf][0] * outscale, acc[mf][nf][1] * outscale);
                *(float2*)(Cf + (size_t)(gr + 8) * N + gc) =
                    make_float2(acc[mf][nf][2] * outscale, acc[mf][nf][3] * outscale);
            }
        }
    }
}

// ---------------------------------------------------------------------------
// Attention v6: 32-key micro-blocks for occupancy 3 (12 warps/SM).
// 128 q/CTA, 4 warps x 32q (2 mf). KV staged 32 rows at a time (16 KB/stage,
// double-buffered). s/P register arrays halved vs v5.
// smem: QH 0 (16K), QL 16K, stage b at 32768+b*16384:
//       KH +0 (4K), KL +4K, VH +8K, VL +12K.  Total 64 KB.
// ---------------------------------------------------------------------------
#define AQH 0
#define AQL 16384
#define AKV 32768
#define A_SMEM 65536
#define EXP_C (0.125f / 65536.f * 1.4426950408889634f)

__global__ __launch_bounds__(128, 3) void attn_f16v6(
    const __half* __restrict__ qkvh, const __half* __restrict__ qkvl,
    __half* __restrict__ ath, __half* __restrict__ atl) {
    extern __shared__ char smc[];

    const int qt = blockIdx.x;     // 0..3
    const int c  = blockIdx.y;     // 0..7
    const int h  = blockIdx.z;     // 0..15
    const int tid  = threadIdx.x;
    const int lane = tid & 31;
    const int w    = tid >> 5;

    const int q0 = qt * 128;
    const int qrow0 = c * WIN + q0;

    const int lm_row  = (lane & 7) + ((lane >> 3) & 1) * 8;
    const int lm_csel = lane >> 4;
    const int gs = (lane >> 4) & 1;
    const int gc2 = (lane >> 3) & 1;
    const uint32_t sb = (uint32_t)__cvta_generic_to_shared(smc);

    const int jb_start = (c == 0) ? (WIN / 32) : 0;
    const int jb_end = ((q0 + 127 + WIN) >> 5) + 1;   // exclusive, <= 32

    // issue K/V loads for 32-key block jb into stage buf (16 KB)
    auto issue_kv = [&](int jb, int buf) {
        const int jbase = c * WIN + jb * 32 - WIN;
        #pragma unroll
        for (int i = 0; i < 8; i++) {
            const int lin = tid + i * 128;    // 0..1023
            const int pl  = lin >> 8;         // 0:KH 1:KL 2:VH 3:VL
            const int rem = lin & 255;
            const int row = rem >> 3;         // 0..31
            const int ch  = rem & 7;
            const __half* src = ((pl & 1) ? qkvl : qkvh)
                + (size_t)(jbase + row) * D3 + ((pl >> 1) ? 2 * DMODEL : DMODEL)
                + h * HDIM + ch * 8;
            const uint32_t dst = sb + AKV + buf * 16384 + pl * 4096 +
                                 row * 128 + ((ch ^ (row & 7)) << 4);
            CP_ASYNC16(dst, src);
        }
        CP_COMMIT();
    };

    // Q tile (128 rows, hi+lo)
    #pragma unroll
    for (int i = 0; i < 16; i++) {
        const int lin = tid + i * 128;
        const int pl  = lin >> 10;
        const int rem = lin & 1023;
        const int row = rem >> 3;
        const int ch  = rem & 7;
        const __half* src = (pl ? qkvl : qkvh)
            + (size_t)(qrow0 + row) * D3 + h * HDIM + ch * 8;
        const uint4 v = *(const uint4*)src;
        *(uint4*)(smc + pl * 16384 + row * 128 + ((ch ^ (row & 7)) << 4)) = v;
    }
    issue_kv(jb_start, 0);

    float o[2][8][4] = {};
    float mrow[2][2] = {{-3e38f, -3e38f}, {-3e38f, -3e38f}};
    float lrow[2][2] = {{0.f, 0.f}, {0.f, 0.f}};

    int buf = 0;
    for (int jb = jb_start; jb < jb_end; jb++) {
        const int j0 = jb * 32;
        CP_WAIT0();
        __syncthreads();
        if (jb + 1 < jb_end) issue_kv(jb + 1, buf ^ 1);

        if (j0 <= q0 + w * 32 + 31 + WIN) {
            const uint32_t kv = sb + AKV + buf * 16384;

            // ---- S = Q K^T : 32q x 32j per warp (raw units) ----
            float s[2][4][4] = {};
            #pragma unroll
            for (int ks = 0; ks < 4; ks++) {
                uint32_t qf[2][2][4];
                #pragma unroll
                for (int mf = 0; mf < 2; mf++) {
                    const int qr = w * 32 + mf * 16 + lm_row;
                    const uint32_t off =
                        (uint32_t)(qr * 128 + (((2 * ks + lm_csel) ^ (qr & 7)) << 4));
                    LDSM_X4(qf[mf][0][0], qf[mf][0][1], qf[mf][0][2], qf[mf][0][3], sb + AQH + off);
                    LDSM_X4(qf[mf][1][0], qf[mf][1][1], qf[mf][1][2], qf[mf][1][3], sb + AQL + off);
                }
                #pragma unroll
                for (int p = 0; p < 2; p++) {
                    const int jr = 8 * (2 * p + gs) + (lane & 7);   // 0..31
                    const uint32_t off =
                        (uint32_t)(jr * 128 + (((2 * ks + gc2) ^ (jr & 7)) << 4));
                    uint32_t rH[4], rL[4];
                    LDSM_X4(rH[0], rH[1], rH[2], rH[3], kv + off);
                    LDSM_X4(rL[0], rL[1], rL[2], rL[3], kv + 4096 + off);
                    #pragma unroll
                    for (int mf = 0; mf < 2; mf++)
                        #pragma unroll
                        for (int s2 = 0; s2 < 2; s2++) {
                            const int nf = 2 * p + s2;
                            MMA_F16(s[mf][nf], qf[mf][0][0], qf[mf][0][1], qf[mf][0][2], qf[mf][0][3], rH[2*s2], rH[2*s2+1]);
                            MMA_F16(s[mf][nf], qf[mf][0][0], qf[mf][0][1], qf[mf][0][2], qf[mf][0][3], rL[2*s2], rL[2*s2+1]);
                            MMA_F16(s[mf][nf], qf[mf][1][0], qf[mf][1][1], qf[mf][1][2], qf[mf][1][3], rH[2*s2], rH[2*s2+1]);
                        }
                }
            }

            const bool needmask = (j0 + 31 > q0 + w * 32 + WIN);

            uint32_t pH[2][2][4], pL[2][2][4];
            #pragma unroll
            for (int mf = 0; mf < 2; mf++) {
                if (needmask) {
                    const int rq0 = q0 + w * 32 + mf * 16 + (lane >> 2);
                    const int rq1 = rq0 + 8;
                    #pragma unroll
                    for (int nf = 0; nf < 4; nf++) {
                        const int col = j0 + nf * 8 + 2 * (lane & 3);
                        if (rq0 + WIN < col)     s[mf][nf][0] = -3e38f;
                        if (rq0 + WIN < col + 1) s[mf][nf][1] = -3e38f;
                        if (rq1 + WIN < col)     s[mf][nf][2] = -3e38f;
                        if (rq1 + WIN < col + 1) s[mf][nf][3] = -3e38f;
                    }
                }
                float mx0 = -3e38f, mx1 = -3e38f;
                #pragma unroll
                for (int nf = 0; nf < 4; nf++) {
                    mx0 = fmaxf(mx0, fmaxf(s[mf][nf][0], s[mf][nf][1]));
                    mx1 = fmaxf(mx1, fmaxf(s[mf][nf][2], s[mf][nf][3]));
                }
                mx0 = fmaxf(mx0, __shfl_xor_sync(0xffffffffu, mx0, 1));
                mx0 = fmaxf(mx0, __shfl_xor_sync(0xffffffffu, mx0, 2));
                mx1 = fmaxf(mx1, __shfl_xor_sync(0xffffffffu, mx1, 1));
                mx1 = fmaxf(mx1, __shfl_xor_sync(0xffffffffu, mx1, 2));
                const float m0n = fmaxf(mrow[mf][0], mx0);
                const float m1n = fmaxf(mrow[mf][1], mx1);
                const float a0 = fexp2((mrow[mf][0] - m0n) * EXP_C);
                const float a1 = fexp2((mrow[mf][1] - m1n) * EXP_C);
                const float b0 = m0n * EXP_C - 11.f;
                const float b1 = m1n * EXP_C - 11.f;
                float sum0 = 0.f, sum1 = 0.f;
                #pragma unroll
                for (int nf = 0; nf < 4; nf++) {
                    s[mf][nf][0] = fexp2(fmaf(s[mf][nf][0], EXP_C, -b0));
                    s[mf][nf][1] = fexp2(fmaf(s[mf][nf][1], EXP_C, -b0));
                    s[mf][nf][2] = fexp2(fmaf(s[mf][nf][2], EXP_C, -b1));
                    s[mf][nf][3] = fexp2(fmaf(s[mf][nf][3], EXP_C, -b1));
                    sum0 += s[mf][nf][0] + s[mf][nf][1];
                    sum1 += s[mf][nf][2] + s[mf][nf][3];
                }
                sum0 += __shfl_xor_sync(0xffffffffu, sum0, 1);
                sum0 += __shfl_xor_sync(0xffffffffu, sum0, 2);
                sum1 += __shfl_xor_sync(0xffffffffu, sum1, 1);
                sum1 += __shfl_xor_sync(0xffffffffu, sum1, 2);
                mrow[mf][0] = m0n; mrow[mf][1] = m1n;
                lrow[mf][0] = lrow[mf][0] * a0 + sum0;
                lrow[mf][1] = lrow[mf][1] * a1 + sum1;
                #pragma unroll
                for (int nf = 0; nf < 8; nf++) {
                    o[mf][nf][0] *= a0; o[mf][nf][1] *= a0;
                    o[mf][nf][2] *= a1; o[mf][nf][3] *= a1;
                }
                #pragma unroll
                for (int kp = 0; kp < 2; kp++) {
                    pH[mf][kp][0] = split_pack(s[mf][2*kp][0],   s[mf][2*kp][1],   pL[mf][kp][0]);
                    pH[mf][kp][1] = split_pack(s[mf][2*kp][2],   s[mf][2*kp][3],   pL[mf][kp][1]);
                    pH[mf][kp][2] = split_pack(s[mf][2*kp+1][0], s[mf][2*kp+1][1], pL[mf][kp][2]);
                    pH[mf][kp][3] = split_pack(s[mf][2*kp+1][2], s[mf][2*kp+1][3], pL[mf][kp][3]);
                }
            }

            // ---- O += P V : V frags shared across both mf ----
            #pragma unroll
            for (int kp = 0; kp < 2; kp++) {
                #pragma unroll
                for (int p2 = 0; p2 < 4; p2++) {
                    const int jr = 16 * kp + 8 * gc2 + (lane & 7);   // 0..31
                    const int ch = 2 * p2 + gs;
                    const uint32_t off =
                        (uint32_t)(jr * 128 + ((ch ^ (jr & 7)) << 4));
                    uint32_t rH[4], rL[4];
                    LDSM_X4_T(rH[0], rH[1], rH[2], rH[3], kv + 8192 + off);
                    LDSM_X4_T(rL[0], rL[1], rL[2], rL[3], kv + 12288 + off);
                    #pragma unroll
                    for (int mf = 0; mf < 2; mf++)
                        #pragma unroll
                        for (int s2 = 0; s2 < 2; s2++) {
                            const int nf = 2 * p2 + s2;
                            MMA_F16(o[mf][nf], pH[mf][kp][0], pH[mf][kp][1], pH[mf][kp][2], pH[mf][kp][3], rH[2*s2], rH[2*s2+1]);
                            MMA_F16(o[mf][nf], pH[mf][kp][0], pH[mf][kp][1], pH[mf][kp][2], pH[mf][kp][3], rL[2*s2], rL[2*s2+1]);
                            MMA_F16(o[mf][nf], pL[mf][kp][0], pL[mf][kp][1], pL[mf][kp][2], pL[mf][kp][3], rH[2*s2], rH[2*s2+1]);
                        }
                }
            }
        }
        buf ^= 1;
    }

    // ---- finalize ----
    #pragma unroll
    for (int mf = 0; mf < 2; mf++) {
        const float inv0 = 1.f / lrow[mf][0];
        const float inv1 = 1.f / lrow[mf][1];
        const int grow0 = qrow0 + w * 32 + mf * 16 + (lane >> 2);
        const int grow1 = grow0 + 8;
        #pragma unroll
        for (int nf = 0; nf < 8; nf++) {
            const int dcol = h * HDIM + nf * 8 + 2 * (lane & 3);
            uint32_t lo;
            uint32_t hi = split_pack(o[mf][nf][0] * inv0, o[mf][nf][1] * inv0, lo);
            *(uint32_t*)(ath + (size_t)grow0 * DMODEL + dcol) = hi;
            *(uint32_t*)(atl + (size_t)grow0 * DMODEL + dcol) = lo;
            hi = split_pack(o[mf][nf][2] * inv1, o[mf][nf][3] * inv1, lo);
            *(uint32_t*)(ath + (size_t)grow1 * DMODEL + dcol) = hi;
            *(uint32_t*)(atl + (size_t)grow1 * DMODEL + dcol) = lo;
        }
    }
}

// ---------------------------------------------------------------------------
extern "C" void kernel_launch(void* const* d_in, const int* in_sizes, int n_in,
                              void* d_out, int out_size) {
    const float* x      = (const float*)d_in[0];
    const float* w_qkv  = (const float*)d_in[1];
    const float* w_out  = (const float*)d_in[2];
    float* out = (float*)d_out;

    __half *qkvh, *qkvl, *xh, *xl, *wqh, *wql, *ath, *atl, *woh, *wol;
    cudaGetSymbolAddress((void**)&qkvh, g_qkvh);
    cudaGetSymbolAddress((void**)&qkvl, g_qkvl);
    cudaGetSymbolAddress((void**)&xh, g_xh);
    cudaGetSymbolAddress((void**)&xl, g_xl);
    cudaGetSymbolAddress((void**)&wqh, g_wqh);
    cudaGetSymbolAddress((void**)&wql, g_wql);
    cudaGetSymbolAddress((void**)&ath, g_ath);
    cudaGetSymbolAddress((void**)&atl, g_atl);
    cudaGetSymbolAddress((void**)&woh, g_woh);
    cudaGetSymbolAddress((void**)&wol, g_wol);

    const int gemm_smem = 65536;
    cudaFuncSetAttribute(gemm_f16x3<true>, cudaFuncAttributeMaxDynamicSharedMemorySize,
                         gemm_smem);
    cudaFuncSetAttribute(gemm_f16x3<false>, cudaFuncAttributeMaxDynamicSharedMemorySize,
                         gemm_smem);
    cudaFuncSetAttribute(attn_f16v6, cudaFuncAttributeMaxDynamicSharedMemorySize,
                         A_SMEM);

    const int NX = SEQ * DMODEL;

    split2h<<<NX / 4 / 256, 256>>>(x, xh, xl, NX);
    split2h_t<<<dim3(D3 / 32, DMODEL / 32), dim3(32, 8)>>>(w_qkv, wqh, wql,
                                                           DMODEL, D3);
    gemm_f16x3<true><<<dim3(D3 / 128, SEQ / 128), 256, gemm_smem>>>(
        xh, xl, wqh, wql, nullptr, qkvh, qkvl, SEQ, D3, DMODEL, 1.f / 256.f);

    attn_f16v6<<<dim3(4, NCHUNK, NHEAD), 128, A_SMEM>>>(qkvh, qkvl, ath, atl);

    split2h_t<<<dim3(DMODEL / 32, DMODEL / 32), dim3(32, 8)>>>(w_out, woh, wol,
                                                               DMODEL, DMODEL);
    gemm_f16x3<false><<<dim3(DMODEL / 128, SEQ / 128), 256, gemm_smem>>>(
        ath, atl, woh, wol, out, nullptr, nullptr, SEQ, DMODEL, DMODEL,
        1.f / 65536.f);
}

// round 13
// speedup vs baseline: 1.0601x; 1.0601x over previous
#include <cuda_runtime.h>
#include <cuda_fp16.h>
#include <cstdint>

// Problem constants
#define SEQ    4096
#define DMODEL 1024
#define D3     3072
#define NHEAD  16
#define HDIM   64
#define WIN    512
#define NCHUNK 8

// Scratch (device globals: allocation-free per harness rules)
__device__ __half g_qkvh[SEQ * D3];           // qkv hi plane (x256)
__device__ __half g_qkvl[SEQ * D3];           // qkv lo plane
__device__ __half g_xh[SEQ * DMODEL];
__device__ __half g_xl[SEQ * DMODEL];
__device__ __half g_wqh[D3 * DMODEL];         // w_qkv^T planes [N][K]
__device__ __half g_wql[D3 * DMODEL];
__device__ __half g_ath[SEQ * DMODEL];        // attn split planes (x256)
__device__ __half g_atl[SEQ * DMODEL];
__device__ __half g_woh[DMODEL * DMODEL];     // w_out^T planes [N][K]
__device__ __half g_wol[DMODEL * DMODEL];

// ---------------------------------------------------------------------------
// helpers
// ---------------------------------------------------------------------------
__device__ __forceinline__ void split_h(float x, __half& hi, __half& lo) {
    hi = __float2half_rn(x);
    lo = __float2half_rn(x - __half2float(hi));
}
__device__ __forceinline__ uint32_t split_pack(float x, float y, uint32_t& lo) {
    __half2 h2 = __float22half2_rn(make_float2(x, y));
    float2 hf = __half22float2(h2);
    __half2 l2 = __float22half2_rn(make_float2(x - hf.x, y - hf.y));
    lo = *reinterpret_cast<uint32_t*>(&l2);
    return *reinterpret_cast<uint32_t*>(&h2);
}
__device__ __forceinline__ float fexp2(float x) {
    float r;
    asm("ex2.approx.f32 %0, %1;" : "=f"(r) : "f"(x));
    return r;
}

#define MMA_F16(d, a0, a1, a2, a3, b0, b1)                                     \
    asm volatile(                                                              \
        "mma.sync.aligned.m16n8k16.row.col.f32.f16.f16.f32 "                   \
        "{%0,%1,%2,%3}, {%4,%5,%6,%7}, {%8,%9}, {%0,%1,%2,%3};"                \
        : "+f"((d)[0]), "+f"((d)[1]), "+f"((d)[2]), "+f"((d)[3])               \
        : "r"(a0), "r"(a1), "r"(a2), "r"(a3), "r"(b0), "r"(b1))

#define LDSM_X4(r0, r1, r2, r3, addr)                                          \
    asm volatile("ldmatrix.sync.aligned.m8n8.x4.shared.b16 {%0,%1,%2,%3}, [%4];" \
        : "=r"(r0), "=r"(r1), "=r"(r2), "=r"(r3) : "r"(addr))

#define LDSM_X4_T(r0, r1, r2, r3, addr)                                        \
    asm volatile("ldmatrix.sync.aligned.m8n8.x4.trans.shared.b16 {%0,%1,%2,%3}, [%4];" \
        : "=r"(r0), "=r"(r1), "=r"(r2), "=r"(r3) : "r"(addr))

#define CP_ASYNC16(dst, src)                                                   \
    asm volatile("cp.async.cg.shared.global [%0], [%1], 16;"                   \
        :: "r"(dst), "l"(src))
#define CP_COMMIT()  asm volatile("cp.async.commit_group;" ::: "memory")
#define CP_WAIT0()   asm volatile("cp.async.wait_group 0;" ::: "memory")

// ---------------------------------------------------------------------------
// Split kernels
// ---------------------------------------------------------------------------
__global__ __launch_bounds__(256) void split2h(const float* __restrict__ in,
                                               __half* __restrict__ hp,
                                               __half* __restrict__ lp, int n) {
    const int idx = (blockIdx.x * 256 + threadIdx.x) * 4;
    if (idx >= n) return;
    const float4 v = *(const float4*)(in + idx);
    uint32_t l0, l1;
    const uint32_t h0 = split_pack(v.x * 256.f, v.y * 256.f, l0);
    const uint32_t h1 = split_pack(v.z * 256.f, v.w * 256.f, l1);
    *(uint2*)(hp + idx) = make_uint2(h0, h1);
    *(uint2*)(lp + idx) = make_uint2(l0, l1);
}

__global__ void split2h_t(const float* __restrict__ w,
                          __half* __restrict__ th, __half* __restrict__ tl,
                          int Kd, int Nd) {
    __shared__ float tile[32][33];
    const int k0 = blockIdx.y * 32, n0 = blockIdx.x * 32;
    const int tx = threadIdx.x, ty = threadIdx.y;
    for (int r = ty; r < 32; r += 8)
        tile[r][tx] = w[(size_t)(k0 + r) * Nd + n0 + tx];
    __syncthreads();
    for (int r = ty; r < 32; r += 8) {
        __half h, l;
        split_h(tile[tx][r] * 256.f, h, l);
        const size_t o = (size_t)(n0 + r) * Kd + k0 + tx;
        th[o] = h; tl[o] = l;
    }
}

// ---------------------------------------------------------------------------
// 3xFP16 GEMM (m16n8k16), cp.async double-buffered.
// R13: B fragments via ldmatrix.x4 (2 per plane per k16) instead of 16 LDS.
// ---------------------------------------------------------------------------
template <bool SPLIT_OUT>
__global__ __launch_bounds__(256, 2) void gemm_f16x3(
    const __half* __restrict__ Ahg, const __half* __restrict__ Alg,
    const __half* __restrict__ Bhg, const __half* __restrict__ Blg,
    float* __restrict__ Cf, __half* __restrict__ Ch, __half* __restrict__ Cl,
    int M, int N, int K, float outscale) {
    extern __shared__ char smc[];

    const int tid  = threadIdx.x;
    const int lane = tid & 31;
    const int warp = tid >> 5;
    const int warp_m = warp >> 2;
    const int warp_n = warp & 3;

    const int m0 = blockIdx.y * 128;
    const int n0 = blockIdx.x * 128;

    const int lm_row  = (lane & 7) + ((lane >> 3) & 1) * 8;
    const int lm_csel = lane >> 4;
    const int gs  = lane >> 4;         // nf-within-ldsm select
    const int gc2 = (lane >> 3) & 1;   // k-chunk select

    float acc[4][4][4] = {};

    const uint32_t sb = (uint32_t)__cvta_generic_to_shared(smc);

    const __half* base0 = Ahg + (size_t)m0 * K;
    const __half* base1 = Alg + (size_t)m0 * K;
    const __half* base2 = Bhg + (size_t)n0 * K;
    const __half* base3 = Blg + (size_t)n0 * K;

    const int NIT = K >> 5;

    auto issue = [&](int it) {
        const int k0 = it << 5;
        const int st4 = (it & 1) << 2;
        #pragma unroll
        for (int i = 0; i < 8; i++) {
            const int lin = tid + i * 256;
            const int pl  = lin >> 9;
            const int rem = lin & 511;
            const int row = rem >> 2;
            const int ch  = rem & 3;
            const __half* src =
                (pl == 0 ? base0 : pl == 1 ? base1 : pl == 2 ? base2 : base3)
                + (size_t)row * K + k0 + ch * 8;
            const uint32_t dst = sb + pl * 16384 + row * 128 +
                                 (((st4 + ch) ^ (row & 7)) << 4);
            CP_ASYNC16(dst, src);
        }
        CP_COMMIT();
    };

    issue(0);
    for (int it = 0; it < NIT; it++) {
        CP_WAIT0();
        __syncthreads();
        if (it + 1 < NIT) issue(it + 1);

        const int st4 = (it & 1) << 2;
        #pragma unroll
        for (int s = 0; s < 2; s++) {
            const int c0 = st4 + 2 * s;
            uint32_t aH[4][4], aL[4][4];
            #pragma unroll
            for (int mf = 0; mf < 4; mf++) {
                const int m = warp_m * 64 + mf * 16 + lm_row;
                const uint32_t off =
                    (uint32_t)(m * 128 + (((c0 + lm_csel) ^ (m & 7)) << 4));
                LDSM_X4(aH[mf][0], aH[mf][1], aH[mf][2], aH[mf][3], sb + off);
                LDSM_X4(aL[mf][0], aL[mf][1], aL[mf][2], aL[mf][3], sb + 16384 + off);
            }
            // B fragments via ldmatrix: 2 x4 per plane cover nf 0..3, both k8 chunks
            uint32_t bH[2][4], bL[2][4];
            #pragma unroll
            for (int p = 0; p < 2; p++) {
                const int n = warp_n * 32 + (2 * p + gs) * 8 + (lane & 7);
                const uint32_t off =
                    (uint32_t)(n * 128 + (((c0 + gc2) ^ (n & 7)) << 4));
                LDSM_X4(bH[p][0], bH[p][1], bH[p][2], bH[p][3], sb + 32768 + off);
                LDSM_X4(bL[p][0], bL[p][1], bL[p][2], bL[p][3], sb + 49152 + off);
            }
            #pragma unroll
            for (int p = 0; p < 2; p++)
                #pragma unroll
                for (int sub = 0; sub < 2; sub++) {
                    const int nf = 2 * p + sub;
                    const uint32_t bh0 = bH[p][2 * sub], bh1 = bH[p][2 * sub + 1];
                    const uint32_t bl0 = bL[p][2 * sub], bl1 = bL[p][2 * sub + 1];
                    #pragma unroll
                    for (int mf = 0; mf < 4; mf++) {
                        MMA_F16(acc[mf][nf], aH[mf][0], aH[mf][1], aH[mf][2], aH[mf][3], bh0, bh1);
                        MMA_F16(acc[mf][nf], aH[mf][0], aH[mf][1], aH[mf][2], aH[mf][3], bl0, bl1);
                        MMA_F16(acc[mf][nf], aL[mf][0], aL[mf][1], aL[mf][2], aL[mf][3], bh0, bh1);
                    }
                }
        }
        __syncthreads();
    }

    const int row_in = lane >> 2;
    const int col_in = 2 * (lane & 3);
    #pragma unroll
    for (int mf = 0; mf < 4; mf++) {
        const int gr = m0 + warp_m * 64 + mf * 16 + row_in;
        #pragma unroll
        for (int nf = 0; nf < 4; nf++) {
            const int gc = n0 + warp_n * 32 + nf * 8 + col_in;
            if (SPLIT_OUT) {
                uint32_t lo;
                uint32_t hi = split_pack(acc[mf][nf][0] * outscale,
                                         acc[mf][nf][1] * outscale, lo);
                *(uint32_t*)(Ch + (size_t)gr * N + gc) = hi;
                *(uint32_t*)(Cl + (size_t)gr * N + gc) = lo;
                hi = split_pack(acc[mf][nf][2] * outscale,
                                acc[mf][nf][3] * outscale, lo);
                *(uint32_t*)(Ch + (size_t)(gr + 8) * N + gc) = hi;
                *(uint32_t*)(Cl + (size_t)(gr + 8) * N + gc) = lo;
            } else {
                *(float2*)(Cf + (size_t)gr * N + gc) =
                    make_float2(acc[mf][nf][0] * outscale, acc[mf][nf][1] * outscale);
                *(float2*)(Cf + (size_t)(gr + 8) * N + gc) =
                    make_float2(acc[mf][nf][2] * outscale, acc[mf][nf][3] * outscale);
            }
        }
    }
}

// ---------------------------------------------------------------------------
// Attention v5 (R11, best known): 64-key blocks, register softmax, exp2
// raw-domain, diagonal-only masking, warp block-skip, cp.async double buffer.
// ---------------------------------------------------------------------------
#define AQH 0
#define AQL 16384
#define AKV 32768
#define A_SMEM (32768 + 2 * 32768)
#define EXP_C (0.125f / 65536.f * 1.4426950408889634f)

__global__ __launch_bounds__(128, 2) void attn_f16v5(
    const __half* __restrict__ qkvh, const __half* __restrict__ qkvl,
    __half* __restrict__ ath, __half* __restrict__ atl) {
    extern __shared__ char smc[];

    const int qt = blockIdx.x;     // 0..3
    const int c  = blockIdx.y;     // 0..7
    const int h  = blockIdx.z;     // 0..15
    const int tid  = threadIdx.x;
    const int lane = tid & 31;
    const int w    = tid >> 5;

    const int q0 = qt * 128;
    const int qrow0 = c * WIN + q0;

    const int lm_row  = (lane & 7) + ((lane >> 3) & 1) * 8;
    const int lm_csel = lane >> 4;
    const int gs = (lane >> 4) & 1;
    const int gc2 = (lane >> 3) & 1;
    const uint32_t sb = (uint32_t)__cvta_generic_to_shared(smc);

    const int kb_start = (c == 0) ? (WIN / 64) : 0;
    const int kb_end = ((q0 + 127 + WIN) >> 6) + 1;

    auto issue_kv = [&](int kb, int buf) {
        const int jbase = c * WIN + kb * 64 - WIN;
        #pragma unroll
        for (int i = 0; i < 16; i++) {
            const int lin = tid + i * 128;
            const int pl  = lin >> 9;
            const int rem = lin & 511;
            const int row = rem >> 3;
            const int ch  = rem & 7;
            const __half* src = ((pl & 1) ? qkvl : qkvh)
                + (size_t)(jbase + row) * D3 + ((pl >> 1) ? 2 * DMODEL : DMODEL)
                + h * HDIM + ch * 8;
            const uint32_t dst = sb + AKV + buf * 32768 + pl * 8192 +
                                 row * 128 + ((ch ^ (row & 7)) << 4);
            CP_ASYNC16(dst, src);
        }
        CP_COMMIT();
    };

    // Q tile
    #pragma unroll
    for (int i = 0; i < 16; i++) {
        const int lin = tid + i * 128;
        const int pl  = lin >> 10;
        const int rem = lin & 1023;
        const int row = rem >> 3;
        const int ch  = rem & 7;
        const __half* src = (pl ? qkvl : qkvh)
            + (size_t)(qrow0 + row) * D3 + h * HDIM + ch * 8;
        const uint4 v = *(const uint4*)src;
        *(uint4*)(smc + pl * 16384 + row * 128 + ((ch ^ (row & 7)) << 4)) = v;
    }
    issue_kv(kb_start, 0);

    float o[2][8][4] = {};
    float mrow[2][2] = {{-1e30f, -1e30f}, {-1e30f, -1e30f}};
    float lrow[2][2] = {{0.f, 0.f}, {0.f, 0.f}};

    int buf = 0;
    for (int kb = kb_start; kb < kb_end; kb++) {
        const int j0 = kb * 64;
        CP_WAIT0();
        __syncthreads();
        if (kb + 1 < kb_end) issue_kv(kb + 1, buf ^ 1);

        if (j0 <= q0 + w * 32 + 31 + WIN) {
            const uint32_t kv = sb + AKV + buf * 32768;

            // ---- S = Q K^T (raw units) ----
            float s[2][8][4] = {};
            #pragma unroll
            for (int ks = 0; ks < 4; ks++) {
                uint32_t qf[2][2][4];
                #pragma unroll
                for (int mf = 0; mf < 2; mf++) {
                    const int qr = w * 32 + mf * 16 + lm_row;
                    const uint32_t off =
                        (uint32_t)(qr * 128 + (((2 * ks + lm_csel) ^ (qr & 7)) << 4));
                    LDSM_X4(qf[mf][0][0], qf[mf][0][1], qf[mf][0][2], qf[mf][0][3], sb + AQH + off);
                    LDSM_X4(qf[mf][1][0], qf[mf][1][1], qf[mf][1][2], qf[mf][1][3], sb + AQL + off);
                }
                #pragma unroll
                for (int p = 0; p < 4; p++) {
                    const int jr = 8 * (2 * p + gs) + (lane & 7);
                    const uint32_t off =
                        (uint32_t)(jr * 128 + (((2 * ks + gc2) ^ (jr & 7)) << 4));
                    uint32_t rH[4], rL[4];
                    LDSM_X4(rH[0], rH[1], rH[2], rH[3], kv + off);
                    LDSM_X4(rL[0], rL[1], rL[2], rL[3], kv + 8192 + off);
                    #pragma unroll
                    for (int mf = 0; mf < 2; mf++)
                        #pragma unroll
                        for (int s2 = 0; s2 < 2; s2++) {
                            const int nf = 2 * p + s2;
                            MMA_F16(s[mf][nf], qf[mf][0][0], qf[mf][0][1], qf[mf][0][2], qf[mf][0][3], rH[2*s2], rH[2*s2+1]);
                            MMA_F16(s[mf][nf], qf[mf][0][0], qf[mf][0][1], qf[mf][0][2], qf[mf][0][3], rL[2*s2], rL[2*s2+1]);
                            MMA_F16(s[mf][nf], qf[mf][1][0], qf[mf][1][1], qf[mf][1][2], qf[mf][1][3], rH[2*s2], rH[2*s2+1]);
                        }
                }
            }

            const bool needmask = (j0 + 63 > q0 + w * 32 + WIN);

            uint32_t pH[2][4][4], pL[2][4][4];
            #pragma unroll
            for (int mf = 0; mf < 2; mf++) {
                if (needmask) {
                    const int rq0 = q0 + w * 32 + mf * 16 + (lane >> 2);
                    const int rq1 = rq0 + 8;
                    #pragma unroll
                    for (int nf = 0; nf < 8; nf++) {
                        const int col = j0 + nf * 8 + 2 * (lane & 3);
                        if (rq0 + WIN < col)     s[mf][nf][0] = -3e38f;
                        if (rq0 + WIN < col + 1) s[mf][nf][1] = -3e38f;
                        if (rq1 + WIN < col)     s[mf][nf][2] = -3e38f;
                        if (rq1 + WIN < col + 1) s[mf][nf][3] = -3e38f;
                    }
                }
                float mx0 = -3e38f, mx1 = -3e38f;
                #pragma unroll
                for (int nf = 0; nf < 8; nf++) {
                    mx0 = fmaxf(mx0, fmaxf(s[mf][nf][0], s[mf][nf][1]));
                    mx1 = fmaxf(mx1, fmaxf(s[mf][nf][2], s[mf][nf][3]));
                }
                mx0 = fmaxf(mx0, __shfl_xor_sync(0xffffffffu, mx0, 1));
                mx0 = fmaxf(mx0, __shfl_xor_sync(0xffffffffu, mx0, 2));
                mx1 = fmaxf(mx1, __shfl_xor_sync(0xffffffffu, mx1, 1));
                mx1 = fmaxf(mx1, __shfl_xor_sync(0xffffffffu, mx1, 2));
                const float m0n = fmaxf(mrow[mf][0], mx0);
                const float m1n = fmaxf(mrow[mf][1], mx1);
                const float a0 = fexp2((mrow[mf][0] - m0n) * EXP_C);
                const float a1 = fexp2((mrow[mf][1] - m1n) * EXP_C);
                const float b0 = m0n * EXP_C - 11.f;
                const float b1 = m1n * EXP_C - 11.f;
                float sum0 = 0.f, sum1 = 0.f;
                #pragma unroll
                for (int nf = 0; nf < 8; nf++) {
                    s[mf][nf][0] = fexp2(fmaf(s[mf][nf][0], EXP_C, -b0));
                    s[mf][nf][1] = fexp2(fmaf(s[mf][nf][1], EXP_C, -b0));
                    s[mf][nf][2] = fexp2(fmaf(s[mf][nf][2], EXP_C, -b1));
                    s[mf][nf][3] = fexp2(fmaf(s[mf][nf][3], EXP_C, -b1));
                    sum0 += s[mf][nf][0] + s[mf][nf][1];
                    sum1 += s[mf][nf][2] + s[mf][nf][3];
                }
                sum0 += __shfl_xor_sync(0xffffffffu, sum0, 1);
                sum0 += __shfl_xor_sync(0xffffffffu, sum0, 2);
                sum1 += __shfl_xor_sync(0xffffffffu, sum1, 1);
                sum1 += __shfl_xor_sync(0xffffffffu, sum1, 2);
                mrow[mf][0] = m0n; mrow[mf][1] = m1n;
                lrow[mf][0] = lrow[mf][0] * a0 + sum0;
                lrow[mf][1] = lrow[mf][1] * a1 + sum1;
                #pragma unroll
                for (int nf = 0; nf < 8; nf++) {
                    o[mf][nf][0] *= a0; o[mf][nf][1] *= a0;
                    o[mf][nf][2] *= a1; o[mf][nf][3] *= a1;
                }
                #pragma unroll
                for (int ks = 0; ks < 4; ks++) {
                    pH[mf][ks][0] = split_pack(s[mf][2*ks][0],   s[mf][2*ks][1],   pL[mf][ks][0]);
                    pH[mf][ks][1] = split_pack(s[mf][2*ks][2],   s[mf][2*ks][3],   pL[mf][ks][1]);
                    pH[mf][ks][2] = split_pack(s[mf][2*ks+1][0], s[mf][2*ks+1][1], pL[mf][ks][2]);
                    pH[mf][ks][3] = split_pack(s[mf][2*ks+1][2], s[mf][2*ks+1][3], pL[mf][ks][3]);
                }
            }

            // ---- O += P V ----
            #pragma unroll
            for (int ks = 0; ks < 4; ks++) {
                #pragma unroll
                for (int p2 = 0; p2 < 4; p2++) {
                    const int jr = 16 * ks + 8 * gc2 + (lane & 7);
                    const int ch = 2 * p2 + gs;
                    const uint32_t off =
                        (uint32_t)(jr * 128 + ((ch ^ (jr & 7)) << 4));
                    uint32_t rH[4], rL[4];
                    LDSM_X4_T(rH[0], rH[1], rH[2], rH[3], kv + 16384 + off);
                    LDSM_X4_T(rL[0], rL[1], rL[2], rL[3], kv + 24576 + off);
                    #pragma unroll
                    for (int mf = 0; mf < 2; mf++)
                        #pragma unroll
                        for (int s2 = 0; s2 < 2; s2++) {
                            const int nf = 2 * p2 + s2;
                            MMA_F16(o[mf][nf], pH[mf][ks][0], pH[mf][ks][1], pH[mf][ks][2], pH[mf][ks][3], rH[2*s2], rH[2*s2+1]);
                            MMA_F16(o[mf][nf], pH[mf][ks][0], pH[mf][ks][1], pH[mf][ks][2], pH[mf][ks][3], rL[2*s2], rL[2*s2+1]);
                            MMA_F16(o[mf][nf], pL[mf][ks][0], pL[mf][ks][1], pL[mf][ks][2], pL[mf][ks][3], rH[2*s2], rH[2*s2+1]);
                        }
                }
            }
        }
        buf ^= 1;
    }

    // ---- finalize ----
    #pragma unroll
    for (int mf = 0; mf < 2; mf++) {
        const float inv0 = 1.f / lrow[mf][0];
        const float inv1 = 1.f / lrow[mf][1];
        const int grow0 = qrow0 + w * 32 + mf * 16 + (lane >> 2);
        const int grow1 = grow0 + 8;
        #pragma unroll
        for (int nf = 0; nf < 8; nf++) {
            const int dcol = h * HDIM + nf * 8 + 2 * (lane & 3);
            uint32_t lo;
            uint32_t hi = split_pack(o[mf][nf][0] * inv0, o[mf][nf][1] * inv0, lo);
            *(uint32_t*)(ath + (size_t)grow0 * DMODEL + dcol) = hi;
            *(uint32_t*)(atl + (size_t)grow0 * DMODEL + dcol) = lo;
            hi = split_pack(o[mf][nf][2] * inv1, o[mf][nf][3] * inv1, lo);
            *(uint32_t*)(ath + (size_t)grow1 * DMODEL + dcol) = hi;
            *(uint32_t*)(atl + (size_t)grow1 * DMODEL + dcol) = lo;
        }
    }
}

// ---------------------------------------------------------------------------
extern "C" void kernel_launch(void* const* d_in, const int* in_sizes, int n_in,
                              void* d_out, int out_size) {
    const float* x      = (const float*)d_in[0];
    const float* w_qkv  = (const float*)d_in[1];
    const float* w_out  = (const float*)d_in[2];
    float* out = (float*)d_out;

    __half *qkvh, *qkvl, *xh, *xl, *wqh, *wql, *ath, *atl, *woh, *wol;
    cudaGetSymbolAddress((void**)&qkvh, g_qkvh);
    cudaGetSymbolAddress((void**)&qkvl, g_qkvl);
    cudaGetSymbolAddress((void**)&xh, g_xh);
    cudaGetSymbolAddress((void**)&xl, g_xl);
    cudaGetSymbolAddress((void**)&wqh, g_wqh);
    cudaGetSymbolAddress((void**)&wql, g_wql);
    cudaGetSymbolAddress((void**)&ath, g_ath);
    cudaGetSymbolAddress((void**)&atl, g_atl);
    cudaGetSymbolAddress((void**)&woh, g_woh);
    cudaGetSymbolAddress((void**)&wol, g_wol);

    const int gemm_smem = 65536;
    cudaFuncSetAttribute(gemm_f16x3<true>, cudaFuncAttributeMaxDynamicSharedMemorySize,
                         gemm_smem);
    cudaFuncSetAttribute(gemm_f16x3<false>, cudaFuncAttributeMaxDynamicSharedMemorySize,
                         gemm_smem);
    cudaFuncSetAttribute(attn_f16v5, cudaFuncAttributeMaxDynamicSharedMemorySize,
                         A_SMEM);

    const int NX = SEQ * DMODEL;

    split2h<<<NX / 4 / 256, 256>>>(x, xh, xl, NX);
    split2h_t<<<dim3(D3 / 32, DMODEL / 32), dim3(32, 8)>>>(w_qkv, wqh, wql,
                                                           DMODEL, D3);
    gemm_f16x3<true><<<dim3(D3 / 128, SEQ / 128), 256, gemm_smem>>>(
        xh, xl, wqh, wql, nullptr, qkvh, qkvl, SEQ, D3, DMODEL, 1.f / 256.f);

    attn_f16v5<<<dim3(4, NCHUNK, NHEAD), 128, A_SMEM>>>(qkvh, qkvl, ath, atl);

    split2h_t<<<dim3(DMODEL / 32, DMODEL / 32), dim3(32, 8)>>>(w_out, woh, wol,
                                                               DMODEL, DMODEL);
    gemm_f16x3<false><<<dim3(DMODEL / 128, SEQ / 128), 256, gemm_smem>>>(
        ath, atl, woh, wol, out, nullptr, nullptr, SEQ, DMODEL, DMODEL,
        1.f / 65536.f);
}

// round 14
// speedup vs baseline: 1.0728x; 1.0120x over previous
#include <cuda_runtime.h>
#include <cuda_fp16.h>
#include <cstdint>

// Problem constants
#define SEQ    4096
#define DMODEL 1024
#define D3     3072
#define NHEAD  16
#define HDIM   64
#define WIN    512
#define NCHUNK 8

// Scratch (device globals: allocation-free per harness rules)
__device__ __half g_qkvh[SEQ * D3];           // qkv hi plane (x256)
__device__ __half g_qkvl[SEQ * D3];           // qkv lo plane
__device__ __half g_xh[SEQ * DMODEL];
__device__ __half g_xl[SEQ * DMODEL];
__device__ __half g_wqh[D3 * DMODEL];         // w_qkv^T planes [N][K]
__device__ __half g_wql[D3 * DMODEL];
__device__ __half g_ath[SEQ * DMODEL];        // attn split planes (x256)
__device__ __half g_atl[SEQ * DMODEL];
__device__ __half g_woh[DMODEL * DMODEL];     // w_out^T planes [N][K]
__device__ __half g_wol[DMODEL * DMODEL];

// ---------------------------------------------------------------------------
// helpers
// ---------------------------------------------------------------------------
__device__ __forceinline__ void split_h(float x, __half& hi, __half& lo) {
    hi = __float2half_rn(x);
    lo = __float2half_rn(x - __half2float(hi));
}
__device__ __forceinline__ uint32_t split_pack(float x, float y, uint32_t& lo) {
    __half2 h2 = __float22half2_rn(make_float2(x, y));
    float2 hf = __half22float2(h2);
    __half2 l2 = __float22half2_rn(make_float2(x - hf.x, y - hf.y));
    lo = *reinterpret_cast<uint32_t*>(&l2);
    return *reinterpret_cast<uint32_t*>(&h2);
}
__device__ __forceinline__ float fexp2(float x) {
    float r;
    asm("ex2.approx.f32 %0, %1;" : "=f"(r) : "f"(x));
    return r;
}

#define MMA_F16(d, a0, a1, a2, a3, b0, b1)                                     \
    asm volatile(                                                              \
        "mma.sync.aligned.m16n8k16.row.col.f32.f16.f16.f32 "                   \
        "{%0,%1,%2,%3}, {%4,%5,%6,%7}, {%8,%9}, {%0,%1,%2,%3};"                \
        : "+f"((d)[0]), "+f"((d)[1]), "+f"((d)[2]), "+f"((d)[3])               \
        : "r"(a0), "r"(a1), "r"(a2), "r"(a3), "r"(b0), "r"(b1))

#define LDSM_X4(r0, r1, r2, r3, addr)                                          \
    asm volatile("ldmatrix.sync.aligned.m8n8.x4.shared.b16 {%0,%1,%2,%3}, [%4];" \
        : "=r"(r0), "=r"(r1), "=r"(r2), "=r"(r3) : "r"(addr))

#define LDSM_X4_T(r0, r1, r2, r3, addr)                                        \
    asm volatile("ldmatrix.sync.aligned.m8n8.x4.trans.shared.b16 {%0,%1,%2,%3}, [%4];" \
        : "=r"(r0), "=r"(r1), "=r"(r2), "=r"(r3) : "r"(addr))

#define CP_ASYNC16(dst, src)                                                   \
    asm volatile("cp.async.cg.shared.global [%0], [%1], 16;"                   \
        :: "r"(dst), "l"(src))
#define CP_COMMIT()  asm volatile("cp.async.commit_group;" ::: "memory")
#define CP_WAIT0()   asm volatile("cp.async.wait_group 0;" ::: "memory")

// ---------------------------------------------------------------------------
// Split kernels
// ---------------------------------------------------------------------------
__global__ __launch_bounds__(256) void split2h(const float* __restrict__ in,
                                               __half* __restrict__ hp,
                                               __half* __restrict__ lp, int n) {
    const int idx = (blockIdx.x * 256 + threadIdx.x) * 4;
    if (idx >= n) return;
    const float4 v = *(const float4*)(in + idx);
    uint32_t l0, l1;
    const uint32_t h0 = split_pack(v.x * 256.f, v.y * 256.f, l0);
    const uint32_t h1 = split_pack(v.z * 256.f, v.w * 256.f, l1);
    *(uint2*)(hp + idx) = make_uint2(h0, h1);
    *(uint2*)(lp + idx) = make_uint2(l0, l1);
}

__global__ void split2h_t(const float* __restrict__ w,
                          __half* __restrict__ th, __half* __restrict__ tl,
                          int Kd, int Nd) {
    __shared__ float tile[32][33];
    const int k0 = blockIdx.y * 32, n0 = blockIdx.x * 32;
    const int tx = threadIdx.x, ty = threadIdx.y;
    for (int r = ty; r < 32; r += 8)
        tile[r][tx] = w[(size_t)(k0 + r) * Nd + n0 + tx];
    __syncthreads();
    for (int r = ty; r < 32; r += 8) {
        __half h, l;
        split_h(tile[tx][r] * 256.f, h, l);
        const size_t o = (size_t)(n0 + r) * Kd + k0 + tx;
        th[o] = h; tl[o] = l;
    }
}

// ---------------------------------------------------------------------------
// 3xFP16 GEMM (m16n8k16), cp.async double-buffered, ldmatrix B (R13).
// ---------------------------------------------------------------------------
template <bool SPLIT_OUT>
__global__ __launch_bounds__(256, 2) void gemm_f16x3(
    const __half* __restrict__ Ahg, const __half* __restrict__ Alg,
    const __half* __restrict__ Bhg, const __half* __restrict__ Blg,
    float* __restrict__ Cf, __half* __restrict__ Ch, __half* __restrict__ Cl,
    int M, int N, int K, float outscale) {
    extern __shared__ char smc[];

    const int tid  = threadIdx.x;
    const int lane = tid & 31;
    const int warp = tid >> 5;
    const int warp_m = warp >> 2;
    const int warp_n = warp & 3;

    const int m0 = blockIdx.y * 128;
    const int n0 = blockIdx.x * 128;

    const int lm_row  = (lane & 7) + ((lane >> 3) & 1) * 8;
    const int lm_csel = lane >> 4;
    const int gs  = lane >> 4;
    const int gc2 = (lane >> 3) & 1;

    float acc[4][4][4] = {};

    const uint32_t sb = (uint32_t)__cvta_generic_to_shared(smc);

    const __half* base0 = Ahg + (size_t)m0 * K;
    const __half* base1 = Alg + (size_t)m0 * K;
    const __half* base2 = Bhg + (size_t)n0 * K;
    const __half* base3 = Blg + (size_t)n0 * K;

    const int NIT = K >> 5;

    auto issue = [&](int it) {
        const int k0 = it << 5;
        const int st4 = (it & 1) << 2;
        #pragma unroll
        for (int i = 0; i < 8; i++) {
            const int lin = tid + i * 256;
            const int pl  = lin >> 9;
            const int rem = lin & 511;
            const int row = rem >> 2;
            const int ch  = rem & 3;
            const __half* src =
                (pl == 0 ? base0 : pl == 1 ? base1 : pl == 2 ? base2 : base3)
                + (size_t)row * K + k0 + ch * 8;
            const uint32_t dst = sb + pl * 16384 + row * 128 +
                                 (((st4 + ch) ^ (row & 7)) << 4);
            CP_ASYNC16(dst, src);
        }
        CP_COMMIT();
    };

    issue(0);
    for (int it = 0; it < NIT; it++) {
        CP_WAIT0();
        __syncthreads();
        if (it + 1 < NIT) issue(it + 1);

        const int st4 = (it & 1) << 2;
        #pragma unroll
        for (int s = 0; s < 2; s++) {
            const int c0 = st4 + 2 * s;
            uint32_t aH[4][4], aL[4][4];
            #pragma unroll
            for (int mf = 0; mf < 4; mf++) {
                const int m = warp_m * 64 + mf * 16 + lm_row;
                const uint32_t off =
                    (uint32_t)(m * 128 + (((c0 + lm_csel) ^ (m & 7)) << 4));
                LDSM_X4(aH[mf][0], aH[mf][1], aH[mf][2], aH[mf][3], sb + off);
                LDSM_X4(aL[mf][0], aL[mf][1], aL[mf][2], aL[mf][3], sb + 16384 + off);
            }
            uint32_t bH[2][4], bL[2][4];
            #pragma unroll
            for (int p = 0; p < 2; p++) {
                const int n = warp_n * 32 + (2 * p + gs) * 8 + (lane & 7);
                const uint32_t off =
                    (uint32_t)(n * 128 + (((c0 + gc2) ^ (n & 7)) << 4));
                LDSM_X4(bH[p][0], bH[p][1], bH[p][2], bH[p][3], sb + 32768 + off);
                LDSM_X4(bL[p][0], bL[p][1], bL[p][2], bL[p][3], sb + 49152 + off);
            }
            #pragma unroll
            for (int p = 0; p < 2; p++)
                #pragma unroll
                for (int sub = 0; sub < 2; sub++) {
                    const int nf = 2 * p + sub;
                    const uint32_t bh0 = bH[p][2 * sub], bh1 = bH[p][2 * sub + 1];
                    const uint32_t bl0 = bL[p][2 * sub], bl1 = bL[p][2 * sub + 1];
                    #pragma unroll
                    for (int mf = 0; mf < 4; mf++) {
                        MMA_F16(acc[mf][nf], aH[mf][0], aH[mf][1], aH[mf][2], aH[mf][3], bh0, bh1);
                        MMA_F16(acc[mf][nf], aH[mf][0], aH[mf][1], aH[mf][2], aH[mf][3], bl0, bl1);
                        MMA_F16(acc[mf][nf], aL[mf][0], aL[mf][1], aL[mf][2], aL[mf][3], bh0, bh1);
                    }
                }
        }
        __syncthreads();
    }

    const int row_in = lane >> 2;
    const int col_in = 2 * (lane & 3);
    #pragma unroll
    for (int mf = 0; mf < 4; mf++) {
        const int gr = m0 + warp_m * 64 + mf * 16 + row_in;
        #pragma unroll
        for (int nf = 0; nf < 4; nf++) {
            const int gc = n0 + warp_n * 32 + nf * 8 + col_in;
            if (SPLIT_OUT) {
                uint32_t lo;
                uint32_t hi = split_pack(acc[mf][nf][0] * outscale,
                                         acc[mf][nf][1] * outscale, lo);
                *(uint32_t*)(Ch + (size_t)gr * N + gc) = hi;
                *(uint32_t*)(Cl + (size_t)gr * N + gc) = lo;
                hi = split_pack(acc[mf][nf][2] * outscale,
                                acc[mf][nf][3] * outscale, lo);
                *(uint32_t*)(Ch + (size_t)(gr + 8) * N + gc) = hi;
                *(uint32_t*)(Cl + (size_t)(gr + 8) * N + gc) = lo;
            } else {
                *(float2*)(Cf + (size_t)gr * N + gc) =
                    make_float2(acc[mf][nf][0] * outscale, acc[mf][nf][1] * outscale);
                *(float2*)(Cf + (size_t)(gr + 8) * N + gc) =
                    make_float2(acc[mf][nf][2] * outscale, acc[mf][nf][3] * outscale);
            }
        }
    }
}

// ---------------------------------------------------------------------------
// Attention v7: 256 threads = 8 warps x 16 q-rows (128 q/CTA), 64-key blocks.
// Halved per-warp register state -> __launch_bounds__(256,2) = 16 warps/SM.
// Heavy-first qt ordering (qt = 3 - blockIdx.x) to shrink the wave tail.
// smem: QH 0 (16K), QL 16K, 2 KV bufs of 32K at 32768+b*32768.  96 KB.
// ---------------------------------------------------------------------------
#define AQH 0
#define AQL 16384
#define AKV 32768
#define A_SMEM (32768 + 2 * 32768)
#define EXP_C (0.125f / 65536.f * 1.4426950408889634f)

__global__ __launch_bounds__(256, 2) void attn_f16v7(
    const __half* __restrict__ qkvh, const __half* __restrict__ qkvl,
    __half* __restrict__ ath, __half* __restrict__ atl) {
    extern __shared__ char smc[];

    const int qt = 3 - blockIdx.x;   // heavy tiles first
    const int c  = blockIdx.y;       // 0..7
    const int h  = blockIdx.z;       // 0..15
    const int tid  = threadIdx.x;
    const int lane = tid & 31;
    const int w    = tid >> 5;       // warp 0..7, owns q rows w*16..w*16+15

    const int q0 = qt * 128;
    const int qrow0 = c * WIN + q0;

    const int lm_row  = (lane & 7) + ((lane >> 3) & 1) * 8;
    const int lm_csel = lane >> 4;
    const int gs = (lane >> 4) & 1;
    const int gc2 = (lane >> 3) & 1;
    const uint32_t sb = (uint32_t)__cvta_generic_to_shared(smc);

    const int kb_start = (c == 0) ? (WIN / 64) : 0;
    const int kb_end = ((q0 + 127 + WIN) >> 6) + 1;

    auto issue_kv = [&](int kb, int buf) {
        const int jbase = c * WIN + kb * 64 - WIN;
        #pragma unroll
        for (int i = 0; i < 8; i++) {
            const int lin = tid + i * 256;    // 0..2047
            const int pl  = lin >> 9;         // 0:KH 1:KL 2:VH 3:VL
            const int rem = lin & 511;
            const int row = rem >> 3;
            const int ch  = rem & 7;
            const __half* src = ((pl & 1) ? qkvl : qkvh)
                + (size_t)(jbase + row) * D3 + ((pl >> 1) ? 2 * DMODEL : DMODEL)
                + h * HDIM + ch * 8;
            const uint32_t dst = sb + AKV + buf * 32768 + pl * 8192 +
                                 row * 128 + ((ch ^ (row & 7)) << 4);
            CP_ASYNC16(dst, src);
        }
        CP_COMMIT();
    };

    // Q tile (128 rows, hi+lo), 256 threads
    #pragma unroll
    for (int i = 0; i < 8; i++) {
        const int lin = tid + i * 256;
        const int pl  = lin >> 10;
        const int rem = lin & 1023;
        const int row = rem >> 3;
        const int ch  = rem & 7;
        const __half* src = (pl ? qkvl : qkvh)
            + (size_t)(qrow0 + row) * D3 + h * HDIM + ch * 8;
        const uint4 v = *(const uint4*)src;
        *(uint4*)(smc + pl * 16384 + row * 128 + ((ch ^ (row & 7)) << 4)) = v;
    }
    issue_kv(kb_start, 0);

    float o[8][4] = {};
    float m0 = -3e38f, m1 = -3e38f, l0r = 0.f, l1r = 0.f;

    const int rq0 = q0 + w * 16 + (lane >> 2);
    const int rq1 = rq0 + 8;

    int buf = 0;
    for (int kb = kb_start; kb < kb_end; kb++) {
        const int j0 = kb * 64;
        CP_WAIT0();
        __syncthreads();
        if (kb + 1 < kb_end) issue_kv(kb + 1, buf ^ 1);

        if (j0 <= q0 + w * 16 + 15 + WIN) {
            const uint32_t kv = sb + AKV + buf * 32768;

            // ---- S = Q K^T : 16q x 64j (raw units) ----
            float s[8][4] = {};
            #pragma unroll
            for (int ks = 0; ks < 4; ks++) {
                uint32_t qH[4], qL[4];
                {
                    const int qr = w * 16 + lm_row;
                    const uint32_t off =
                        (uint32_t)(qr * 128 + (((2 * ks + lm_csel) ^ (qr & 7)) << 4));
                    LDSM_X4(qH[0], qH[1], qH[2], qH[3], sb + AQH + off);
                    LDSM_X4(qL[0], qL[1], qL[2], qL[3], sb + AQL + off);
                }
                #pragma unroll
                for (int p = 0; p < 4; p++) {
                    const int jr = 8 * (2 * p + gs) + (lane & 7);
                    const uint32_t off =
                        (uint32_t)(jr * 128 + (((2 * ks + gc2) ^ (jr & 7)) << 4));
                    uint32_t rH[4], rL[4];
                    LDSM_X4(rH[0], rH[1], rH[2], rH[3], kv + off);
                    LDSM_X4(rL[0], rL[1], rL[2], rL[3], kv + 8192 + off);
                    #pragma unroll
                    for (int s2 = 0; s2 < 2; s2++) {
                        const int nf = 2 * p + s2;
                        MMA_F16(s[nf], qH[0], qH[1], qH[2], qH[3], rH[2*s2], rH[2*s2+1]);
                        MMA_F16(s[nf], qH[0], qH[1], qH[2], qH[3], rL[2*s2], rL[2*s2+1]);
                        MMA_F16(s[nf], qL[0], qL[1], qL[2], qL[3], rH[2*s2], rH[2*s2+1]);
                    }
                }
            }

            // ---- diagonal-only mask ----
            if (j0 + 63 > q0 + w * 16 + WIN) {
                #pragma unroll
                for (int nf = 0; nf < 8; nf++) {
                    const int col = j0 + nf * 8 + 2 * (lane & 3);
                    if (rq0 + WIN < col)     s[nf][0] = -3e38f;
                    if (rq0 + WIN < col + 1) s[nf][1] = -3e38f;
                    if (rq1 + WIN < col)     s[nf][2] = -3e38f;
                    if (rq1 + WIN < col + 1) s[nf][3] = -3e38f;
                }
            }

            // ---- register softmax (raw-domain exp2) ----
            float mx0 = -3e38f, mx1 = -3e38f;
            #pragma unroll
            for (int nf = 0; nf < 8; nf++) {
                mx0 = fmaxf(mx0, fmaxf(s[nf][0], s[nf][1]));
                mx1 = fmaxf(mx1, fmaxf(s[nf][2], s[nf][3]));
            }
            mx0 = fmaxf(mx0, __shfl_xor_sync(0xffffffffu, mx0, 1));
            mx0 = fmaxf(mx0, __shfl_xor_sync(0xffffffffu, mx0, 2));
            mx1 = fmaxf(mx1, __shfl_xor_sync(0xffffffffu, mx1, 1));
            mx1 = fmaxf(mx1, __shfl_xor_sync(0xffffffffu, mx1, 2));
            const float m0n = fmaxf(m0, mx0);
            const float m1n = fmaxf(m1, mx1);
            const float a0 = fexp2((m0 - m0n) * EXP_C);
            const float a1 = fexp2((m1 - m1n) * EXP_C);
            const float b0 = m0n * EXP_C - 11.f;
            const float b1 = m1n * EXP_C - 11.f;
            float sum0 = 0.f, sum1 = 0.f;
            #pragma unroll
            for (int nf = 0; nf < 8; nf++) {
                s[nf][0] = fexp2(fmaf(s[nf][0], EXP_C, -b0));
                s[nf][1] = fexp2(fmaf(s[nf][1], EXP_C, -b0));
                s[nf][2] = fexp2(fmaf(s[nf][2], EXP_C, -b1));
                s[nf][3] = fexp2(fmaf(s[nf][3], EXP_C, -b1));
                sum0 += s[nf][0] + s[nf][1];
                sum1 += s[nf][2] + s[nf][3];
            }
            sum0 += __shfl_xor_sync(0xffffffffu, sum0, 1);
            sum0 += __shfl_xor_sync(0xffffffffu, sum0, 2);
            sum1 += __shfl_xor_sync(0xffffffffu, sum1, 1);
            sum1 += __shfl_xor_sync(0xffffffffu, sum1, 2);
            m0 = m0n; m1 = m1n;
            l0r = l0r * a0 + sum0;
            l1r = l1r * a1 + sum1;
            #pragma unroll
            for (int nf = 0; nf < 8; nf++) {
                o[nf][0] *= a0; o[nf][1] *= a0;
                o[nf][2] *= a1; o[nf][3] *= a1;
            }
            uint32_t pH[4][4], pL[4][4];
            #pragma unroll
            for (int ks = 0; ks < 4; ks++) {
                pH[ks][0] = split_pack(s[2*ks][0],   s[2*ks][1],   pL[ks][0]);
                pH[ks][1] = split_pack(s[2*ks][2],   s[2*ks][3],   pL[ks][1]);
                pH[ks][2] = split_pack(s[2*ks+1][0], s[2*ks+1][1], pL[ks][2]);
                pH[ks][3] = split_pack(s[2*ks+1][2], s[2*ks+1][3], pL[ks][3]);
            }

            // ---- O += P V ----
            #pragma unroll
            for (int ks = 0; ks < 4; ks++) {
                #pragma unroll
                for (int p2 = 0; p2 < 4; p2++) {
                    const int jr = 16 * ks + 8 * gc2 + (lane & 7);
                    const int ch = 2 * p2 + gs;
                    const uint32_t off =
                        (uint32_t)(jr * 128 + ((ch ^ (jr & 7)) << 4));
                    uint32_t rH[4], rL[4];
                    LDSM_X4_T(rH[0], rH[1], rH[2], rH[3], kv + 16384 + off);
                    LDSM_X4_T(rL[0], rL[1], rL[2], rL[3], kv + 24576 + off);
                    #pragma unroll
                    for (int s2 = 0; s2 < 2; s2++) {
                        const int nf = 2 * p2 + s2;
                        MMA_F16(o[nf], pH[ks][0], pH[ks][1], pH[ks][2], pH[ks][3], rH[2*s2], rH[2*s2+1]);
                        MMA_F16(o[nf], pH[ks][0], pH[ks][1], pH[ks][2], pH[ks][3], rL[2*s2], rL[2*s2+1]);
                        MMA_F16(o[nf], pL[ks][0], pL[ks][1], pL[ks][2], pL[ks][3], rH[2*s2], rH[2*s2+1]);
                    }
                }
            }
        }
        buf ^= 1;
    }

    // ---- finalize ----
    const float inv0 = 1.f / l0r;
    const float inv1 = 1.f / l1r;
    const int grow0 = qrow0 + w * 16 + (lane >> 2);
    const int grow1 = grow0 + 8;
    #pragma unroll
    for (int nf = 0; nf < 8; nf++) {
        const int dcol = h * HDIM + nf * 8 + 2 * (lane & 3);
        uint32_t lo;
        uint32_t hi = split_pack(o[nf][0] * inv0, o[nf][1] * inv0, lo);
        *(uint32_t*)(ath + (size_t)grow0 * DMODEL + dcol) = hi;
        *(uint32_t*)(atl + (size_t)grow0 * DMODEL + dcol) = lo;
        hi = split_pack(o[nf][2] * inv1, o[nf][3] * inv1, lo);
        *(uint32_t*)(ath + (size_t)grow1 * DMODEL + dcol) = hi;
        *(uint32_t*)(atl + (size_t)grow1 * DMODEL + dcol) = lo;
    }
}

// ---------------------------------------------------------------------------
extern "C" void kernel_launch(void* const* d_in, const int* in_sizes, int n_in,
                              void* d_out, int out_size) {
    const float* x      = (const float*)d_in[0];
    const float* w_qkv  = (const float*)d_in[1];
    const float* w_out  = (const float*)d_in[2];
    float* out = (float*)d_out;

    __half *qkvh, *qkvl, *xh, *xl, *wqh, *wql, *ath, *atl, *woh, *wol;
    cudaGetSymbolAddress((void**)&qkvh, g_qkvh);
    cudaGetSymbolAddress((void**)&qkvl, g_qkvl);
    cudaGetSymbolAddress((void**)&xh, g_xh);
    cudaGetSymbolAddress((void**)&xl, g_xl);
    cudaGetSymbolAddress((void**)&wqh, g_wqh);
    cudaGetSymbolAddress((void**)&wql, g_wql);
    cudaGetSymbolAddress((void**)&ath, g_ath);
    cudaGetSymbolAddress((void**)&atl, g_atl);
    cudaGetSymbolAddress((void**)&woh, g_woh);
    cudaGetSymbolAddress((void**)&wol, g_wol);

    const int gemm_smem = 65536;
    cudaFuncSetAttribute(gemm_f16x3<true>, cudaFuncAttributeMaxDynamicSharedMemorySize,
                         gemm_smem);
    cudaFuncSetAttribute(gemm_f16x3<false>, cudaFuncAttributeMaxDynamicSharedMemorySize,
                         gemm_smem);
    cudaFuncSetAttribute(attn_f16v7, cudaFuncAttributeMaxDynamicSharedMemorySize,
                         A_SMEM);

    const int NX = SEQ * DMODEL;

    split2h<<<NX / 4 / 256, 256>>>(x, xh, xl, NX);
    split2h_t<<<dim3(D3 / 32, DMODEL / 32), dim3(32, 8)>>>(w_qkv, wqh, wql,
                                                           DMODEL, D3);
    gemm_f16x3<true><<<dim3(D3 / 128, SEQ / 128), 256, gemm_smem>>>(
        xh, xl, wqh, wql, nullptr, qkvh, qkvl, SEQ, D3, DMODEL, 1.f / 256.f);

    attn_f16v7<<<dim3(4, NCHUNK, NHEAD), 256, A_SMEM>>>(qkvh, qkvl, ath, atl);

    split2h_t<<<dim3(DMODEL / 32, DMODEL / 32), dim3(32, 8)>>>(w_out, woh, wol,
                                                               DMODEL, DMODEL);
    gemm_f16x3<false><<<dim3(DMODEL / 128, SEQ / 128), 256, gemm_smem>>>(
        ath, atl, woh, wol, out, nullptr, nullptr, SEQ, DMODEL, DMODEL,
        1.f / 65536.f);
}